// round 16
// baseline (speedup 1.0000x reference)
#include <cuda_runtime.h>
#include <cuda_bf16.h>
#include <math.h>

// ---------------------------------------------------------------------------
// Problem constants
// ---------------------------------------------------------------------------
#define B_    4
#define S_    512
#define T_    16
#define D_    512
#define DS_   64
#define V_    32000
#define NTOK  2048              // B_*S_
#define NROWS 32768             // B_*T_*S_
#define DECAY 0.60653065971263342f   // exp(-1/2)
#define NBLK  128               // persistent state kernel grid

static const long SPK       = (long)NROWS * D_;   // 16,777,216 floats
static const long LOGITS_SZ = (long)NTOK * V_;    // 65,536,000 floats
static const long H_SZ      = SPK;

// arena offsets (floats).  Hall placed in the interior so speculative
// prefetches beyond its end stay inside the arena.
static const long OFF_HALL = 0;                             // 32768 x 64
static const long OFF_SPK0 = OFF_HALL + (long)NROWS * DS_;
static const long OFF_SPK1 = OFF_SPK0 + SPK;
static const long OFF_XP   = OFF_SPK1 + SPK;
static const long OFF_Q    = OFF_XP + SPK;        // doubles as OU (32768x512)
static const long OFF_K    = OFF_Q + SPK;
static const long OFF_V    = OFF_K + SPK;
static const long OFF_HM   = OFF_V + SPK;                   // 2048 x 512
static const long OFF_CNT  = OFF_HM + (long)NTOK * D_;      // ints: 16*64
static const long CNT_INTS = 16 * 64;
static const long OFF_BAR  = OFF_CNT + CNT_INTS;            // 16 ints
static const long OFF_FLG  = OFF_BAR + 16;                  // 48 ints
static const long ARENA_TOTAL = OFF_FLG + 64;

__device__ __align__(256) float g_arena[ARENA_TOTAL];

// persistent state kernel smem layout (floats)
#define SM_AT    0                    // At[n][m] : 64 x 65
#define SM_BT    (64 * 65)            // Bt[d][m] : 512 x 65
#define SM_XS    (SM_BT + 512 * 65)   // xs[tk][d]: 16 x 512
#define SM_HS    (SM_XS + 16 * 512)   // hs[tk][m]: 16 x 68
#define SM_INT   (SM_HS + 16 * 68)    // scnt[64] + sflag[16]
#define SM_TOTAL (SM_INT + 80)
static const int SMEM_STATE_BYTES = SM_TOTAL * 4;   // 187,520 B

// ===========================================================================
// SSM SECTION -- LIF arithmetic BITWISE-IDENTICAL to R13 (passing).
// ===========================================================================

__global__ void encode_k(const int* __restrict__ ids, const float* __restrict__ emb,
                         const float* __restrict__ scaling,
                         float* __restrict__ spk, int* __restrict__ flag)
{
    int idx = blockIdx.x * blockDim.x + threadIdx.x;   // over NTOK*D_
    int d   = idx & (D_ - 1);
    int tok = idx >> 9;
    int b   = tok >> 9;
    int s   = tok & (S_ - 1);
    float e = emb[(long)ids[tok] * D_ + d];
    float a = 1.0f / (1.0f + expf(-(*scaling) * e));
    float tr = rintf(10.0f * (1.0f - a));
    int ti = (int)tr;
    if (ti < 0) ti = 0;
    if (ti > T_ - 1) ti = T_ - 1;
    spk[(((long)(b * T_ + ti)) * S_ + s) * D_ + d] = 1.0f;
    flag[ti] = 1;
}

// Persistent per-layer state recurrence: 128 blocks x 256 threads, 1/SM.
__global__ __launch_bounds__(256)
void state_layer_k(const float* __restrict__ spk_in,
                   const float* __restrict__ Amat, const float* __restrict__ Bmat,
                   int* __restrict__ cnt, const int* __restrict__ flags,
                   float* __restrict__ Hall, int* __restrict__ bar)
{
    extern __shared__ float sm[];
    float* At = sm + SM_AT;
    float* Bt = sm + SM_BT;
    float* xs = sm + SM_XS;
    float* hs = sm + SM_HS;
    int*   scnt  = (int*)(sm + SM_INT);
    int*   sflag = scnt + 64;

    const int tid  = threadIdx.x;
    const int m    = tid & 63;
    const int lt   = tid >> 6;          // 0..3
    const int tok0 = blockIdx.x * 16;

    for (int i = tid; i < DS_ * DS_; i += 256) {
        int r = i >> 6, n = i & 63;
        At[n * 65 + r] = Amat[i];
    }
    for (int i = tid; i < DS_ * D_; i += 256) {
        int mm = i >> 9, d = i & (D_ - 1);
        Bt[d * 65 + mm] = Bmat[i];
    }
    for (int i = tid; i < 16 * 68; i += 256) hs[i] = 0.0f;
    if (tid < 16) sflag[tid] = flags[tid];
    __syncthreads();

    float v[4];
#pragma unroll
    for (int j = 0; j < 4; ++j) v[j] = 0.0f;
    float thr = 1.0f;

    for (int t = 0; t < T_; ++t) {
        const int active = sflag[t];
        if (tid < 64) scnt[tid] = 0;
        if (active) {
            for (int i = tid; i < 16 * D_; i += 256) {
                int tk = i >> 9, d = i & (D_ - 1);
                int tok = tok0 + tk;
                int b = tok >> 9, s = tok & (S_ - 1);
                xs[tk * D_ + d] = spk_in[(((long)(b * T_ + t)) * S_ + s) * D_ + d];
            }
        }
        __syncthreads();

        float acc[4];
#pragma unroll
        for (int j = 0; j < 4; ++j) acc[j] = 0.0f;

        for (int n = 0; n < DS_; n += 4) {
            float a0 = At[(n + 0) * 65 + m];
            float a1 = At[(n + 1) * 65 + m];
            float a2 = At[(n + 2) * 65 + m];
            float a3 = At[(n + 3) * 65 + m];
#pragma unroll
            for (int j = 0; j < 4; ++j) {
                float4 hv = *(const float4*)&hs[(lt + 4 * j) * 68 + n];
                acc[j] += hv.x * a0;
                acc[j] += hv.y * a1;
                acc[j] += hv.z * a2;
                acc[j] += hv.w * a3;
            }
        }
        if (active) {
            for (int d = 0; d < D_; d += 4) {
                float b0 = Bt[(d + 0) * 65 + m];
                float b1 = Bt[(d + 1) * 65 + m];
                float b2 = Bt[(d + 2) * 65 + m];
                float b3 = Bt[(d + 3) * 65 + m];
#pragma unroll
                for (int j = 0; j < 4; ++j) {
                    float4 xv = *(const float4*)&xs[(lt + 4 * j) * D_ + d];
                    acc[j] += xv.x * b0;
                    acc[j] += xv.y * b1;
                    acc[j] += xv.z * b2;
                    acc[j] += xv.w * b3;
                }
            }
        }
        __syncthreads();

        int c = 0;
#pragma unroll
        for (int j = 0; j < 4; ++j) {
            int tk = lt + 4 * j;
            int tok = tok0 + tk;
            float vv = v[j] * DECAY + acc[j];
            float sp = (vv - thr >= 0.0f) ? 1.0f : 0.0f;
            v[j] = vv * (1.0f - sp);
            hs[tk * 68 + m] = sp;
            int b = tok >> 9, s = tok & (S_ - 1);
            Hall[(((long)(b * T_ + t)) * S_ + s) * DS_ + m] = sp;
            c += (int)sp;
        }
        if (c) atomicAdd(&scnt[m], c);
        __syncthreads();
        if (tid < 64 && scnt[tid]) atomicAdd(&cnt[t * 64 + tid], scnt[tid]);
        __threadfence();
        if (tid == 0) {
            atomicAdd(bar, 1);
            while (*((volatile int*)bar) < NBLK * (t + 1)) { }
        }
        __syncthreads();
        {
            float mean = (float)(*((volatile int*)&cnt[t * 64 + m])) * (1.0f / 2048.0f);
            thr += 0.1f * (mean - 0.1f);
        }
        __syncthreads();
    }
}

// Fused output LIF over all 16 steps (unchanged -- passing).
__global__ __launch_bounds__(256)
void out_fused_k(const float* __restrict__ OU, const int* __restrict__ flags,
                 float* __restrict__ spk_out, int* __restrict__ flags_next)
{
    const int tid = threadIdx.x;
    const int el  = tid & 3;
    const int e   = blockIdx.x * 4 + el;
    const int ts  = tid >> 2;                 // 0..63
    __shared__ int scnt[4];

    float v[32];
#pragma unroll
    for (int j = 0; j < 32; ++j) v[j] = 0.0f;
    float thr = 1.0f;

    for (int t = 0; t < T_; ++t) {
        int act = flags[t];
        if (tid < 4) scnt[tid] = 0;
        __syncthreads();
        if (act) {
            int c = 0;
#pragma unroll
            for (int j = 0; j < 32; ++j) {
                int tok = ts + 64 * j;
                int b = tok >> 9, s = tok & (S_ - 1);
                long row = (long)b * (T_ * S_) + (long)t * S_ + s;
                float vv = v[j] * DECAY + OU[row * D_ + e];
                float sp = (vv - thr >= 0.0f) ? 1.0f : 0.0f;
                v[j] = vv * (1.0f - sp);
                spk_out[row * D_ + e] = sp;
                c += (int)sp;
            }
            if (c) atomicAdd(&scnt[el], c);
        } else {
#pragma unroll
            for (int j = 0; j < 32; ++j) {
                int tok = ts + 64 * j;
                int b = tok >> 9, s = tok & (S_ - 1);
                long row = (long)b * (T_ * S_) + (long)t * S_ + s;
                spk_out[row * D_ + e] = 0.0f;
            }
        }
        __syncthreads();
        if (act) {
            int cc = scnt[el];
            float mean = (float)cc * (1.0f / 2048.0f);
            thr += 0.1f * (mean - 0.1f);
            if (tid == 0 && (scnt[0] | scnt[1] | scnt[2] | scnt[3]))
                flags_next[t] = 1;
        }
        __syncthreads();
    }
}

// fp32 SGEMM -- double-buffered; FFMA chain bitwise == R13 (passing).
// Prefetch index clamped to a valid tile on the last iteration (no OOB).
template<bool ACC, bool HASBIAS>
__global__ __launch_bounds__(256)
void sgemm_k(const float* __restrict__ A, const float* __restrict__ W,
             const float* __restrict__ bias, float* __restrict__ C,
             int M, int N, int K,
             long aOuter, long aInner, long aConst, int aSdiv,
             const int* __restrict__ tflags)
{
    const int bx = blockIdx.x, by = blockIdx.y;
    if (tflags && tflags[(by >> 2) & (T_ - 1)] == 0) return;

    __shared__ float As[2][8][128];
    __shared__ float Bs[2][8][128];
    const int tid = threadIdx.x;
    const int tx = tid & 15, ty = tid >> 4;

    const int lrow = tid >> 1;
    const int lk4  = (tid & 1) * 4;

    const int arow = by * 128 + lrow;
    const long aoff = (long)(arow / aSdiv) * aOuter + (long)(arow % aSdiv) * aInner + aConst;
    const float* Aptr = A + aoff + lk4;
    const float* Wptr = W + (long)(bx * 128 + lrow) * K + lk4;

    float acc[8][8];
#pragma unroll
    for (int i = 0; i < 8; ++i)
#pragma unroll
        for (int j = 0; j < 8; ++j) acc[i][j] = 0.0f;

    {
        float4 av = *(const float4*)(Aptr);
        float4 wv = *(const float4*)(Wptr);
        As[0][lk4 + 0][lrow] = av.x; As[0][lk4 + 1][lrow] = av.y;
        As[0][lk4 + 2][lrow] = av.z; As[0][lk4 + 3][lrow] = av.w;
        Bs[0][lk4 + 0][lrow] = wv.x; Bs[0][lk4 + 1][lrow] = wv.y;
        Bs[0][lk4 + 2][lrow] = wv.z; Bs[0][lk4 + 3][lrow] = wv.w;
    }
    __syncthreads();

    const int ntiles = K / 8;
    for (int tile = 0; tile < ntiles; ++tile) {
        const int cur = tile & 1;
        const bool more = (tile + 1 < ntiles);
        const int pf = more ? (tile + 1) : tile;   // clamped: always in-bounds
        float4 av = *(const float4*)(Aptr + pf * 8);
        float4 wv = *(const float4*)(Wptr + pf * 8);
#pragma unroll
        for (int k = 0; k < 8; ++k) {
            float ar[8], br[8];
            *(float4*)&ar[0] = *(const float4*)&As[cur][k][ty * 4];
            *(float4*)&ar[4] = *(const float4*)&As[cur][k][64 + ty * 4];
            *(float4*)&br[0] = *(const float4*)&Bs[cur][k][tx * 4];
            *(float4*)&br[4] = *(const float4*)&Bs[cur][k][64 + tx * 4];
#pragma unroll
            for (int i = 0; i < 8; ++i)
#pragma unroll
                for (int j = 0; j < 8; ++j)
                    acc[i][j] += ar[i] * br[j];
        }
        if (more) {
            const int nxt = cur ^ 1;
            As[nxt][lk4 + 0][lrow] = av.x; As[nxt][lk4 + 1][lrow] = av.y;
            As[nxt][lk4 + 2][lrow] = av.z; As[nxt][lk4 + 3][lrow] = av.w;
            Bs[nxt][lk4 + 0][lrow] = wv.x; Bs[nxt][lk4 + 1][lrow] = wv.y;
            Bs[nxt][lk4 + 2][lrow] = wv.z; Bs[nxt][lk4 + 3][lrow] = wv.w;
        }
        __syncthreads();
    }

#pragma unroll
    for (int i = 0; i < 8; ++i) {
        int row = by * 128 + ((i < 4) ? (ty * 4 + i) : (64 + ty * 4 + (i - 4)));
        float* crow = C + (long)row * N + bx * 128;
#pragma unroll
        for (int half = 0; half < 2; ++half) {
            int colbase = half * 64 + tx * 4;
            float4 r;
            r.x = acc[i][half * 4 + 0]; r.y = acc[i][half * 4 + 1];
            r.z = acc[i][half * 4 + 2]; r.w = acc[i][half * 4 + 3];
            if (HASBIAS) {
                float4 bv = *(const float4*)(bias + bx * 128 + colbase);
                r.x += bv.x; r.y += bv.y; r.z += bv.z; r.w += bv.w;
            }
            if (ACC) {
                float4 ov = *(const float4*)(crow + colbase);
                r.x += ov.x; r.y += ov.y; r.z += ov.z; r.w += ov.w;
            }
            *(float4*)(crow + colbase) = r;
        }
    }
}

// ===========================================================================
// TENSOR-CORE SECTION -- single-pass tf32, double-buffered, tf32 bits
// PRE-CONVERTED at staging (same rounding + same mma order as R13 => outputs
// bitwise identical). PERM=true reads A rows from (B,T,S,D) spike layout,
// eliminating the transpose pass. Prefetch index clamped (no OOB).
// ===========================================================================
__device__ __forceinline__ unsigned f2tf(float x) {
    unsigned u;
    asm("cvt.rna.tf32.f32 %0, %1;" : "=r"(u) : "f"(x));
    return u;
}

__device__ __forceinline__ float4 tf4(float4 v) {
    float4 r;
    r.x = __uint_as_float(f2tf(v.x));
    r.y = __uint_as_float(f2tf(v.y));
    r.z = __uint_as_float(f2tf(v.z));
    r.w = __uint_as_float(f2tf(v.w));
    return r;
}

__device__ __forceinline__ void mma8(float* c, const unsigned* a, const unsigned* b) {
    asm volatile(
        "mma.sync.aligned.m16n8k8.row.col.f32.tf32.tf32.f32 "
        "{%0,%1,%2,%3},{%4,%5,%6,%7},{%8,%9},{%0,%1,%2,%3};"
        : "+f"(c[0]), "+f"(c[1]), "+f"(c[2]), "+f"(c[3])
        : "r"(a[0]), "r"(a[1]), "r"(a[2]), "r"(a[3]), "r"(b[0]), "r"(b[1]));
}

template<bool HASBIAS, bool PERM>
__global__ __launch_bounds__(256)
void gemm_tf32_k(const float* __restrict__ A, const float* __restrict__ W,
                 const float* __restrict__ bias, float* __restrict__ C,
                 int M, int N, int K)
{
    constexpr int BM = 128, BN = 128, BK = 16;
    constexpr int MT = 4, NT = 4;
    __shared__ float As[2][BK][BM + 8];
    __shared__ float Bs[2][BK][BN + 8];

    const int tid  = threadIdx.x;
    const int warp = tid >> 5, lane = tid & 31;
    const int wm = warp & 1, wn = warp >> 1;
    const int mW = wm * 64, nW = wn * 32;
    const int g = lane >> 2, q = lane & 3;
    const int bx = blockIdx.x, by = blockIdx.y;

    const int lr = tid >> 1;
    const int lk = (tid & 1) * 8;
    long aoff;
    if (PERM) {
        // A row index is in (B,S,T) order; data lives in (B,T,S,D) layout.
        int row = by * BM + lr;
        int tq = row & (T_ - 1);
        int token = row >> 4;
        int b = token >> 9, s = token & (S_ - 1);
        aoff = (((long)(b * T_ + tq)) * S_ + s) * D_;
    } else {
        aoff = (long)(by * BM + lr) * K;
    }
    const float* Ag = A + aoff + lk;
    const float* Wg = W + (long)(bx * BN + lr) * K + lk;

    float acc[MT][NT][4];
#pragma unroll
    for (int i = 0; i < MT; ++i)
#pragma unroll
        for (int j = 0; j < NT; ++j)
#pragma unroll
            for (int r = 0; r < 4; ++r) acc[i][j][r] = 0.0f;

    // prologue: tile 0 -> buf 0 (store tf32-rounded bits)
    {
        float4 a0 = tf4(*(const float4*)(Ag));
        float4 a1 = tf4(*(const float4*)(Ag + 4));
        As[0][lk + 0][lr] = a0.x; As[0][lk + 1][lr] = a0.y;
        As[0][lk + 2][lr] = a0.z; As[0][lk + 3][lr] = a0.w;
        As[0][lk + 4][lr] = a1.x; As[0][lk + 5][lr] = a1.y;
        As[0][lk + 6][lr] = a1.z; As[0][lk + 7][lr] = a1.w;
        float4 w0 = tf4(*(const float4*)(Wg));
        float4 w1 = tf4(*(const float4*)(Wg + 4));
        Bs[0][lk + 0][lr] = w0.x; Bs[0][lk + 1][lr] = w0.y;
        Bs[0][lk + 2][lr] = w0.z; Bs[0][lk + 3][lr] = w0.w;
        Bs[0][lk + 4][lr] = w1.x; Bs[0][lk + 5][lr] = w1.y;
        Bs[0][lk + 6][lr] = w1.z; Bs[0][lk + 7][lr] = w1.w;
    }
    __syncthreads();

    const int ntiles = K / BK;
    for (int tile = 0; tile < ntiles; ++tile) {
        const int cur = tile & 1;
        const bool more = (tile + 1 < ntiles);
        const int pf = more ? (tile + 1) : tile;   // clamped: always in-bounds
        float4 a0 = *(const float4*)(Ag + pf * BK);
        float4 a1 = *(const float4*)(Ag + pf * BK + 4);
        float4 w0 = *(const float4*)(Wg + pf * BK);
        float4 w1 = *(const float4*)(Wg + pf * BK + 4);
#pragma unroll
        for (int ks = 0; ks < BK; ks += 8) {
            unsigned af[MT][4];
            unsigned bf[NT][2];
#pragma unroll
            for (int i = 0; i < MT; ++i) {
                int m = mW + i * 16 + g;
                af[i][0] = __float_as_uint(As[cur][ks + q][m]);
                af[i][1] = __float_as_uint(As[cur][ks + q][m + 8]);
                af[i][2] = __float_as_uint(As[cur][ks + 4 + q][m]);
                af[i][3] = __float_as_uint(As[cur][ks + 4 + q][m + 8]);
            }
#pragma unroll
            for (int j = 0; j < NT; ++j) {
                int n = nW + j * 8 + g;
                bf[j][0] = __float_as_uint(Bs[cur][ks + q][n]);
                bf[j][1] = __float_as_uint(Bs[cur][ks + 4 + q][n]);
            }
#pragma unroll
            for (int i = 0; i < MT; ++i)
#pragma unroll
                for (int j = 0; j < NT; ++j)
                    mma8(acc[i][j], af[i], bf[j]);
        }
        if (more) {
            const int nxt = cur ^ 1;
            a0 = tf4(a0); a1 = tf4(a1); w0 = tf4(w0); w1 = tf4(w1);
            As[nxt][lk + 0][lr] = a0.x; As[nxt][lk + 1][lr] = a0.y;
            As[nxt][lk + 2][lr] = a0.z; As[nxt][lk + 3][lr] = a0.w;
            As[nxt][lk + 4][lr] = a1.x; As[nxt][lk + 5][lr] = a1.y;
            As[nxt][lk + 6][lr] = a1.z; As[nxt][lk + 7][lr] = a1.w;
            Bs[nxt][lk + 0][lr] = w0.x; Bs[nxt][lk + 1][lr] = w0.y;
            Bs[nxt][lk + 2][lr] = w0.z; Bs[nxt][lk + 3][lr] = w0.w;
            Bs[nxt][lk + 4][lr] = w1.x; Bs[nxt][lk + 5][lr] = w1.y;
            Bs[nxt][lk + 6][lr] = w1.z; Bs[nxt][lk + 7][lr] = w1.w;
        }
        __syncthreads();
    }

#pragma unroll
    for (int i = 0; i < MT; ++i) {
        int r0 = by * BM + mW + i * 16 + g;
#pragma unroll
        for (int j = 0; j < NT; ++j) {
            int c0 = bx * BN + nW + j * 8 + q * 2;
            float2 lo; lo.x = acc[i][j][0]; lo.y = acc[i][j][1];
            float2 hi; hi.x = acc[i][j][2]; hi.y = acc[i][j][3];
            if (HASBIAS) {
                float2 bv = *(const float2*)(bias + c0);
                lo.x += bv.x; lo.y += bv.y; hi.x += bv.x; hi.y += bv.y;
            }
            *(float2*)(C + (long)r0 * N + c0)       = lo;
            *(float2*)(C + (long)(r0 + 8) * N + c0) = hi;
        }
    }
}

// ---------------------------------------------------------------------------
// Attention core per (token, head)
// ---------------------------------------------------------------------------
__global__ __launch_bounds__(128)
void attn_core_k(const float* __restrict__ q, const float* __restrict__ k,
                 const float* __restrict__ v, float* __restrict__ av)
{
    __shared__ float qs[16][128], ks[16][128], vsm[16][128];
    __shared__ float sc[16][17];
    const int tid = threadIdx.x;
    const long token = blockIdx.x >> 2;
    const int h = blockIdx.x & 3;
    const long base = token * 16 * 512 + h * 128;

#pragma unroll
    for (int t = 0; t < 16; ++t) {
        qs[t][tid]  = q[base + (long)t * 512 + tid];
        ks[t][tid]  = k[base + (long)t * 512 + tid];
        vsm[t][tid] = v[base + (long)t * 512 + tid];
    }
    __syncthreads();

    for (int p = tid; p < 256; p += 128) {
        int t = p >> 4, u = p & 15;
        float acc = 0.0f;
#pragma unroll
        for (int d = 0; d < 128; ++d) acc += qs[t][d] * ks[u][d];
        sc[t][u] = acc / 11.3137084989847612f;   // / sqrt(128)
    }
    __syncthreads();

    if (tid < 16) {
        int t = tid;
        float mx = sc[t][0];
#pragma unroll
        for (int u = 1; u < 16; ++u) mx = fmaxf(mx, sc[t][u]);
        float e[16], sum = 0.0f;
#pragma unroll
        for (int u = 0; u < 16; ++u) { e[u] = expf(sc[t][u] - mx); sum += e[u]; }
#pragma unroll
        for (int u = 0; u < 16; ++u) sc[t][u] = e[u] / sum;
    }
    __syncthreads();

#pragma unroll
    for (int t = 0; t < 16; ++t) {
        float acc = 0.0f;
#pragma unroll
        for (int u = 0; u < 16; ++u) acc += sc[t][u] * vsm[u][tid];
        av[base + (long)t * 512 + tid] = acc;
    }
}

// ---------------------------------------------------------------------------
// h = x + permute(out_attn); hmean = mean_t(h)
// ---------------------------------------------------------------------------
__global__ void finalize_k(const float* __restrict__ xspk, const float* __restrict__ oat,
                           float* __restrict__ hout, float* __restrict__ hmean)
{
    int idx = blockIdx.x * blockDim.x + threadIdx.x;  // over NTOK*D_
    int d   = idx & (D_ - 1);
    int tok = idx >> 9;
    int b   = tok >> 9;
    int s   = tok & (S_ - 1);
    float sum = 0.0f;
#pragma unroll
    for (int t = 0; t < 16; ++t) {
        long hidx = (((long)(b * T_ + t)) * S_ + s) * D_ + d;
        float val = xspk[hidx] + oat[(((long)tok) * T_ + t) * D_ + d];
        hout[hidx] = val;
        sum += val;
    }
    hmean[(long)tok * D_ + d] = sum * (1.0f / 16.0f);
}

// ---------------------------------------------------------------------------
// host
// ---------------------------------------------------------------------------
extern "C" void kernel_launch(void* const* d_in, const int* in_sizes, int n_in,
                              void* d_out, int out_size)
{
    const int*   ids  = (const int*)d_in[0];
    const float* emb  = (const float*)d_in[1];
    const float* scal = (const float*)d_in[2];
    const float* Aall = (const float*)d_in[3];
    const float* Ball = (const float*)d_in[4];
    const float* Call = (const float*)d_in[5];
    const float* Dall = (const float*)d_in[6];
    const float* wq = (const float*)d_in[7];   const float* bq = (const float*)d_in[8];
    const float* wk = (const float*)d_in[9];   const float* bk = (const float*)d_in[10];
    const float* wv = (const float*)d_in[11];  const float* bv = (const float*)d_in[12];
    const float* wo = (const float*)d_in[13];  const float* bo = (const float*)d_in[14];
    const float* wout = (const float*)d_in[15];const float* bout = (const float*)d_in[16];
    float* out = (float*)d_out;

    float* arena = nullptr;
    cudaGetSymbolAddress((void**)&arena, g_arena);

    float* Hall   = arena + OFF_HALL;
    float* spk0   = arena + OFF_SPK0;
    float* spk1   = arena + OFF_SPK1;
    float* xp     = arena + OFF_XP;
    float* qb     = arena + OFF_Q;     // OU during SSM phase
    float* kb     = arena + OFF_K;
    float* vb     = arena + OFF_V;
    float* hmean  = arena + OFF_HM;
    int*   cnt    = (int*)(arena + OFF_CNT);   // 16*64 state counts
    int*   bar    = (int*)(arena + OFF_BAR);
    int*   flags  = (int*)(arena + OFF_FLG);
    float* OU     = qb;

    cudaFuncSetAttribute(state_layer_k,
                         cudaFuncAttributeMaxDynamicSharedMemorySize,
                         SMEM_STATE_BYTES);

    // -------- encode --------
    cudaMemsetAsync(spk0, 0, SPK * sizeof(float));
    cudaMemsetAsync(flags, 0, 48 * sizeof(int));
    encode_k<<<(NTOK * D_) / 256, 256>>>(ids, emb, scal, spk0, flags);

    // -------- SSM layers --------
    for (int l = 0; l < 2; ++l) {
        const float* Al = Aall + (long)l * DS_ * DS_;
        const float* Bl = Ball + (long)l * DS_ * D_;
        const float* Cl = Call + (long)l * D_ * DS_;
        const float* Dl = Dall + (long)l * D_ * D_;
        float* xin  = l ? spk1 : spk0;
        float* xout = l ? spk0 : spk1;
        int* fin  = flags + (l ? 16 : 0);
        int* fout = flags + (l ? 32 : 16);

        cudaMemsetAsync(cnt, 0, (CNT_INTS + 16) * sizeof(int));

        // persistent state recurrence: all 16 steps in one launch
        state_layer_k<<<NBLK, 256, SMEM_STATE_BYTES>>>(
            xin, Al, Bl, cnt, fin, Hall, bar);

        // hoisted output-path GEMMs (chains bitwise == R13); inactive-t rows skipped
        sgemm_k<false, false><<<dim3(4, NROWS / 128), 256>>>(
            Hall, Cl, nullptr, OU, NROWS, D_, DS_,
            (long)NROWS * DS_, (long)DS_, 0L, NROWS, fin);
        sgemm_k<true, false><<<dim3(4, NROWS / 128), 256>>>(
            xin, Dl, nullptr, OU, NROWS, D_, D_,
            (long)NROWS * D_, (long)D_, 0L, NROWS, fin);

        // fused output LIF over all 16 steps (writes zeros on inactive steps)
        out_fused_k<<<D_ / 4, 256>>>(OU, fin, xout, fout);
    }
    // after 2 layers: attention input = spk0 (B,T,S,D)

    // -------- attention (single-pass tf32; A read directly via PERM) --------
    const int MA = NROWS;  // 32768
    gemm_tf32_k<true, true><<<dim3(D_ / 128, MA / 128), 256>>>(spk0, wq, bq, qb, MA, D_, D_);
    gemm_tf32_k<true, true><<<dim3(D_ / 128, MA / 128), 256>>>(spk0, wk, bk, kb, MA, D_, D_);
    gemm_tf32_k<true, true><<<dim3(D_ / 128, MA / 128), 256>>>(spk0, wv, bv, vb, MA, D_, D_);
    attn_core_k<<<NTOK * 4, 128>>>(qb, kb, vb, spk1);           // av -> spk1
    gemm_tf32_k<true, false><<<dim3(D_ / 128, MA / 128), 256>>>(spk1, wo, bo, kb, MA, D_, D_);

    // -------- residual + mean + outputs --------
    float* hout = ((long)out_size >= LOGITS_SZ + H_SZ) ? (out + LOGITS_SZ) : xp;
    finalize_k<<<(NTOK * D_) / 256, 256>>>(spk0, kb, hout, hmean);

    // logits (single-pass tf32)
    gemm_tf32_k<true, false><<<dim3(V_ / 128, NTOK / 128), 256>>>(
        hmean, wout, bout, out, NTOK, V_, D_);
}

// round 17
// speedup vs baseline: 1.0809x; 1.0809x over previous
#include <cuda_runtime.h>
#include <cuda_bf16.h>
#include <math.h>

// ---------------------------------------------------------------------------
// Problem constants
// ---------------------------------------------------------------------------
#define B_    4
#define S_    512
#define T_    16
#define D_    512
#define DS_   64
#define V_    32000
#define NTOK  2048              // B_*S_
#define NROWS 32768             // B_*T_*S_
#define DECAY 0.60653065971263342f   // exp(-1/2)
#define NBLK  128               // persistent state kernel grid

static const long SPK       = (long)NROWS * D_;   // 16,777,216 floats
static const long LOGITS_SZ = (long)NTOK * V_;    // 65,536,000 floats
static const long H_SZ      = SPK;

// arena offsets (floats).  Hall interior (safety margin for any speculation).
static const long OFF_HALL = 0;                             // 32768 x 64
static const long OFF_SPK0 = OFF_HALL + (long)NROWS * DS_;
static const long OFF_SPK1 = OFF_SPK0 + SPK;
static const long OFF_XP   = OFF_SPK1 + SPK;                // hout fallback
static const long OFF_Q    = OFF_XP + SPK;        // doubles as OU (32768x512)
static const long OFF_K    = OFF_Q + SPK;
static const long OFF_V    = OFF_K + SPK;
static const long OFF_HM   = OFF_V + SPK;                   // 2048 x 512
static const long OFF_CNT  = OFF_HM + (long)NTOK * D_;      // ints: 16*64
static const long CNT_INTS = 16 * 64;
static const long OFF_BAR  = OFF_CNT + CNT_INTS;            // 16 ints
static const long OFF_FLG  = OFF_BAR + 16;                  // 48 ints
static const long ARENA_TOTAL = OFF_FLG + 64;

__device__ __align__(256) float g_arena[ARENA_TOTAL];

// persistent state kernel smem layout (floats)
#define SM_AT    0                    // At[n][m] : 64 x 65
#define SM_BT    (64 * 65)            // Bt[d][m] : 512 x 65
#define SM_XS    (SM_BT + 512 * 65)   // xs[tk][d]: 16 x 512
#define SM_HS    (SM_XS + 16 * 512)   // hs[tk][m]: 16 x 68
#define SM_INT   (SM_HS + 16 * 68)    // scnt[64] + sflag[16]
#define SM_TOTAL (SM_INT + 80)
static const int SMEM_STATE_BYTES = SM_TOTAL * 4;   // 187,520 B

// ===========================================================================
// SSM SECTION -- LIF arithmetic BITWISE-IDENTICAL to R13 (passing).
// ===========================================================================

__global__ void encode_k(const int* __restrict__ ids, const float* __restrict__ emb,
                         const float* __restrict__ scaling,
                         float* __restrict__ spk, int* __restrict__ flag)
{
    int idx = blockIdx.x * blockDim.x + threadIdx.x;   // over NTOK*D_
    int d   = idx & (D_ - 1);
    int tok = idx >> 9;
    int b   = tok >> 9;
    int s   = tok & (S_ - 1);
    float e = emb[(long)ids[tok] * D_ + d];
    float a = 1.0f / (1.0f + expf(-(*scaling) * e));
    float tr = rintf(10.0f * (1.0f - a));
    int ti = (int)tr;
    if (ti < 0) ti = 0;
    if (ti > T_ - 1) ti = T_ - 1;
    spk[(((long)(b * T_ + ti)) * S_ + s) * D_ + d] = 1.0f;
    flag[ti] = 1;
}

// Persistent per-layer state recurrence: 128 blocks x 256 threads, 1/SM.
__global__ __launch_bounds__(256)
void state_layer_k(const float* __restrict__ spk_in,
                   const float* __restrict__ Amat, const float* __restrict__ Bmat,
                   int* __restrict__ cnt, const int* __restrict__ flags,
                   float* __restrict__ Hall, int* __restrict__ bar)
{
    extern __shared__ float sm[];
    float* At = sm + SM_AT;
    float* Bt = sm + SM_BT;
    float* xs = sm + SM_XS;
    float* hs = sm + SM_HS;
    int*   scnt  = (int*)(sm + SM_INT);
    int*   sflag = scnt + 64;

    const int tid  = threadIdx.x;
    const int m    = tid & 63;
    const int lt   = tid >> 6;          // 0..3
    const int tok0 = blockIdx.x * 16;

    for (int i = tid; i < DS_ * DS_; i += 256) {
        int r = i >> 6, n = i & 63;
        At[n * 65 + r] = Amat[i];
    }
    for (int i = tid; i < DS_ * D_; i += 256) {
        int mm = i >> 9, d = i & (D_ - 1);
        Bt[d * 65 + mm] = Bmat[i];
    }
    for (int i = tid; i < 16 * 68; i += 256) hs[i] = 0.0f;
    if (tid < 16) sflag[tid] = flags[tid];
    __syncthreads();

    float v[4];
#pragma unroll
    for (int j = 0; j < 4; ++j) v[j] = 0.0f;
    float thr = 1.0f;

    for (int t = 0; t < T_; ++t) {
        const int active = sflag[t];
        if (tid < 64) scnt[tid] = 0;
        if (active) {
            for (int i = tid; i < 16 * D_; i += 256) {
                int tk = i >> 9, d = i & (D_ - 1);
                int tok = tok0 + tk;
                int b = tok >> 9, s = tok & (S_ - 1);
                xs[tk * D_ + d] = spk_in[(((long)(b * T_ + t)) * S_ + s) * D_ + d];
            }
        }
        __syncthreads();

        float acc[4];
#pragma unroll
        for (int j = 0; j < 4; ++j) acc[j] = 0.0f;

        for (int n = 0; n < DS_; n += 4) {
            float a0 = At[(n + 0) * 65 + m];
            float a1 = At[(n + 1) * 65 + m];
            float a2 = At[(n + 2) * 65 + m];
            float a3 = At[(n + 3) * 65 + m];
#pragma unroll
            for (int j = 0; j < 4; ++j) {
                float4 hv = *(const float4*)&hs[(lt + 4 * j) * 68 + n];
                acc[j] += hv.x * a0;
                acc[j] += hv.y * a1;
                acc[j] += hv.z * a2;
                acc[j] += hv.w * a3;
            }
        }
        if (active) {
            for (int d = 0; d < D_; d += 4) {
                float b0 = Bt[(d + 0) * 65 + m];
                float b1 = Bt[(d + 1) * 65 + m];
                float b2 = Bt[(d + 2) * 65 + m];
                float b3 = Bt[(d + 3) * 65 + m];
#pragma unroll
                for (int j = 0; j < 4; ++j) {
                    float4 xv = *(const float4*)&xs[(lt + 4 * j) * D_ + d];
                    acc[j] += xv.x * b0;
                    acc[j] += xv.y * b1;
                    acc[j] += xv.z * b2;
                    acc[j] += xv.w * b3;
                }
            }
        }
        __syncthreads();

        int c = 0;
#pragma unroll
        for (int j = 0; j < 4; ++j) {
            int tk = lt + 4 * j;
            int tok = tok0 + tk;
            float vv = v[j] * DECAY + acc[j];
            float sp = (vv - thr >= 0.0f) ? 1.0f : 0.0f;
            v[j] = vv * (1.0f - sp);
            hs[tk * 68 + m] = sp;
            int b = tok >> 9, s = tok & (S_ - 1);
            Hall[(((long)(b * T_ + t)) * S_ + s) * DS_ + m] = sp;
            c += (int)sp;
        }
        if (c) atomicAdd(&scnt[m], c);
        __syncthreads();
        if (tid < 64 && scnt[tid]) atomicAdd(&cnt[t * 64 + tid], scnt[tid]);
        __threadfence();
        if (tid == 0) {
            atomicAdd(bar, 1);
            while (*((volatile int*)bar) < NBLK * (t + 1)) { }
        }
        __syncthreads();
        {
            float mean = (float)(*((volatile int*)&cnt[t * 64 + m])) * (1.0f / 2048.0f);
            thr += 0.1f * (mean - 0.1f);
        }
        __syncthreads();
    }
}

// Fused output LIF over all 16 steps (unchanged -- passing).
__global__ __launch_bounds__(256)
void out_fused_k(const float* __restrict__ OU, const int* __restrict__ flags,
                 float* __restrict__ spk_out, int* __restrict__ flags_next)
{
    const int tid = threadIdx.x;
    const int el  = tid & 3;
    const int e   = blockIdx.x * 4 + el;
    const int ts  = tid >> 2;                 // 0..63
    __shared__ int scnt[4];

    float v[32];
#pragma unroll
    for (int j = 0; j < 32; ++j) v[j] = 0.0f;
    float thr = 1.0f;

    for (int t = 0; t < T_; ++t) {
        int act = flags[t];
        if (tid < 4) scnt[tid] = 0;
        __syncthreads();
        if (act) {
            int c = 0;
#pragma unroll
            for (int j = 0; j < 32; ++j) {
                int tok = ts + 64 * j;
                int b = tok >> 9, s = tok & (S_ - 1);
                long row = (long)b * (T_ * S_) + (long)t * S_ + s;
                float vv = v[j] * DECAY + OU[row * D_ + e];
                float sp = (vv - thr >= 0.0f) ? 1.0f : 0.0f;
                v[j] = vv * (1.0f - sp);
                spk_out[row * D_ + e] = sp;
                c += (int)sp;
            }
            if (c) atomicAdd(&scnt[el], c);
        } else {
#pragma unroll
            for (int j = 0; j < 32; ++j) {
                int tok = ts + 64 * j;
                int b = tok >> 9, s = tok & (S_ - 1);
                long row = (long)b * (T_ * S_) + (long)t * S_ + s;
                spk_out[row * D_ + e] = 0.0f;
            }
        }
        __syncthreads();
        if (act) {
            int cc = scnt[el];
            float mean = (float)cc * (1.0f / 2048.0f);
            thr += 0.1f * (mean - 0.1f);
            if (tid == 0 && (scnt[0] | scnt[1] | scnt[2] | scnt[3]))
                flags_next[t] = 1;
        }
        __syncthreads();
    }
}

// fp32 SGEMM -- double-buffered, conditional prefetch (EXACT R13 structure;
// FFMA chain bitwise == R13). Per-t gating via tflags.
template<bool ACC, bool HASBIAS>
__global__ __launch_bounds__(256)
void sgemm_k(const float* __restrict__ A, const float* __restrict__ W,
             const float* __restrict__ bias, float* __restrict__ C,
             int M, int N, int K,
             long aOuter, long aInner, long aConst, int aSdiv,
             const int* __restrict__ tflags)
{
    const int bx = blockIdx.x, by = blockIdx.y;
    if (tflags && tflags[(by >> 2) & (T_ - 1)] == 0) return;

    __shared__ float As[2][8][128];
    __shared__ float Bs[2][8][128];
    const int tid = threadIdx.x;
    const int tx = tid & 15, ty = tid >> 4;

    const int lrow = tid >> 1;
    const int lk4  = (tid & 1) * 4;

    const int arow = by * 128 + lrow;
    const long aoff = (long)(arow / aSdiv) * aOuter + (long)(arow % aSdiv) * aInner + aConst;
    const float* Aptr = A + aoff + lk4;
    const float* Wptr = W + (long)(bx * 128 + lrow) * K + lk4;

    float acc[8][8];
#pragma unroll
    for (int i = 0; i < 8; ++i)
#pragma unroll
        for (int j = 0; j < 8; ++j) acc[i][j] = 0.0f;

    {
        float4 av = *(const float4*)(Aptr);
        float4 wv = *(const float4*)(Wptr);
        As[0][lk4 + 0][lrow] = av.x; As[0][lk4 + 1][lrow] = av.y;
        As[0][lk4 + 2][lrow] = av.z; As[0][lk4 + 3][lrow] = av.w;
        Bs[0][lk4 + 0][lrow] = wv.x; Bs[0][lk4 + 1][lrow] = wv.y;
        Bs[0][lk4 + 2][lrow] = wv.z; Bs[0][lk4 + 3][lrow] = wv.w;
    }
    __syncthreads();

    const int ntiles = K / 8;
    for (int tile = 0; tile < ntiles; ++tile) {
        const int cur = tile & 1;
        float4 av, wv;
        const bool more = (tile + 1 < ntiles);
        if (more) {
            av = *(const float4*)(Aptr + (tile + 1) * 8);
            wv = *(const float4*)(Wptr + (tile + 1) * 8);
        }
#pragma unroll
        for (int k = 0; k < 8; ++k) {
            float ar[8], br[8];
            *(float4*)&ar[0] = *(const float4*)&As[cur][k][ty * 4];
            *(float4*)&ar[4] = *(const float4*)&As[cur][k][64 + ty * 4];
            *(float4*)&br[0] = *(const float4*)&Bs[cur][k][tx * 4];
            *(float4*)&br[4] = *(const float4*)&Bs[cur][k][64 + tx * 4];
#pragma unroll
            for (int i = 0; i < 8; ++i)
#pragma unroll
                for (int j = 0; j < 8; ++j)
                    acc[i][j] += ar[i] * br[j];
        }
        if (more) {
            const int nxt = cur ^ 1;
            As[nxt][lk4 + 0][lrow] = av.x; As[nxt][lk4 + 1][lrow] = av.y;
            As[nxt][lk4 + 2][lrow] = av.z; As[nxt][lk4 + 3][lrow] = av.w;
            Bs[nxt][lk4 + 0][lrow] = wv.x; Bs[nxt][lk4 + 1][lrow] = wv.y;
            Bs[nxt][lk4 + 2][lrow] = wv.z; Bs[nxt][lk4 + 3][lrow] = wv.w;
        }
        __syncthreads();
    }

#pragma unroll
    for (int i = 0; i < 8; ++i) {
        int row = by * 128 + ((i < 4) ? (ty * 4 + i) : (64 + ty * 4 + (i - 4)));
        float* crow = C + (long)row * N + bx * 128;
#pragma unroll
        for (int half = 0; half < 2; ++half) {
            int colbase = half * 64 + tx * 4;
            float4 r;
            r.x = acc[i][half * 4 + 0]; r.y = acc[i][half * 4 + 1];
            r.z = acc[i][half * 4 + 2]; r.w = acc[i][half * 4 + 3];
            if (HASBIAS) {
                float4 bv = *(const float4*)(bias + bx * 128 + colbase);
                r.x += bv.x; r.y += bv.y; r.z += bv.z; r.w += bv.w;
            }
            if (ACC) {
                float4 ov = *(const float4*)(crow + colbase);
                r.x += ov.x; r.y += ov.y; r.z += ov.z; r.w += ov.w;
            }
            *(float4*)(crow + colbase) = r;
        }
    }
}

// ===========================================================================
// TENSOR-CORE SECTION -- single-pass tf32, double-buffered, cvt at consume
// (EXACT R13 structure; mma sequence identical => bitwise-identical outputs).
// PERM=true reads A rows directly from (B,T,S,D) spike layout (row index in
// (B,S,T) order) -- pure addressing change eliminating the transpose pass.
// ===========================================================================
__device__ __forceinline__ unsigned f2tf(float x) {
    unsigned u;
    asm("cvt.rna.tf32.f32 %0, %1;" : "=r"(u) : "f"(x));
    return u;
}

__device__ __forceinline__ void mma8(float* c, const unsigned* a, const unsigned* b) {
    asm volatile(
        "mma.sync.aligned.m16n8k8.row.col.f32.tf32.tf32.f32 "
        "{%0,%1,%2,%3},{%4,%5,%6,%7},{%8,%9},{%0,%1,%2,%3};"
        : "+f"(c[0]), "+f"(c[1]), "+f"(c[2]), "+f"(c[3])
        : "r"(a[0]), "r"(a[1]), "r"(a[2]), "r"(a[3]), "r"(b[0]), "r"(b[1]));
}

template<bool HASBIAS, bool PERM>
__global__ __launch_bounds__(256)
void gemm_tf32_k(const float* __restrict__ A, const float* __restrict__ W,
                 const float* __restrict__ bias, float* __restrict__ C,
                 int M, int N, int K)
{
    constexpr int BM = 128, BN = 128, BK = 16;
    constexpr int MT = 4, NT = 4;
    __shared__ float As[2][BK][BM + 8];
    __shared__ float Bs[2][BK][BN + 8];

    const int tid  = threadIdx.x;
    const int warp = tid >> 5, lane = tid & 31;
    const int wm = warp & 1, wn = warp >> 1;
    const int mW = wm * 64, nW = wn * 32;
    const int g = lane >> 2, q = lane & 3;
    const int bx = blockIdx.x, by = blockIdx.y;

    const int lr = tid >> 1;
    const int lk = (tid & 1) * 8;
    long aoff;
    if (PERM) {
        // A row index is in (B,S,T) order; data lives in (B,T,S,D) layout.
        int row = by * BM + lr;
        int tq = row & (T_ - 1);
        int token = row >> 4;
        int b = token >> 9, s = token & (S_ - 1);
        aoff = (((long)(b * T_ + tq)) * S_ + s) * D_;
    } else {
        aoff = (long)(by * BM + lr) * K;
    }
    const float* Ag = A + aoff + lk;
    const float* Wg = W + (long)(bx * BN + lr) * K + lk;

    float acc[MT][NT][4];
#pragma unroll
    for (int i = 0; i < MT; ++i)
#pragma unroll
        for (int j = 0; j < NT; ++j)
#pragma unroll
            for (int r = 0; r < 4; ++r) acc[i][j][r] = 0.0f;

    // prologue: tile 0 -> buf 0
    {
        float4 a0 = *(const float4*)(Ag);
        float4 a1 = *(const float4*)(Ag + 4);
        As[0][lk + 0][lr] = a0.x; As[0][lk + 1][lr] = a0.y;
        As[0][lk + 2][lr] = a0.z; As[0][lk + 3][lr] = a0.w;
        As[0][lk + 4][lr] = a1.x; As[0][lk + 5][lr] = a1.y;
        As[0][lk + 6][lr] = a1.z; As[0][lk + 7][lr] = a1.w;
        float4 w0 = *(const float4*)(Wg);
        float4 w1 = *(const float4*)(Wg + 4);
        Bs[0][lk + 0][lr] = w0.x; Bs[0][lk + 1][lr] = w0.y;
        Bs[0][lk + 2][lr] = w0.z; Bs[0][lk + 3][lr] = w0.w;
        Bs[0][lk + 4][lr] = w1.x; Bs[0][lk + 5][lr] = w1.y;
        Bs[0][lk + 6][lr] = w1.z; Bs[0][lk + 7][lr] = w1.w;
    }
    __syncthreads();

    const int ntiles = K / BK;
    for (int tile = 0; tile < ntiles; ++tile) {
        const int cur = tile & 1;
        const bool more = (tile + 1 < ntiles);
        float4 a0, a1, w0, w1;
        if (more) {
            a0 = *(const float4*)(Ag + (tile + 1) * BK);
            a1 = *(const float4*)(Ag + (tile + 1) * BK + 4);
            w0 = *(const float4*)(Wg + (tile + 1) * BK);
            w1 = *(const float4*)(Wg + (tile + 1) * BK + 4);
        }
#pragma unroll
        for (int ks = 0; ks < BK; ks += 8) {
            unsigned af[MT][4];
            unsigned bf[NT][2];
#pragma unroll
            for (int i = 0; i < MT; ++i) {
                int m = mW + i * 16 + g;
                af[i][0] = f2tf(As[cur][ks + q][m]);
                af[i][1] = f2tf(As[cur][ks + q][m + 8]);
                af[i][2] = f2tf(As[cur][ks + 4 + q][m]);
                af[i][3] = f2tf(As[cur][ks + 4 + q][m + 8]);
            }
#pragma unroll
            for (int j = 0; j < NT; ++j) {
                int n = nW + j * 8 + g;
                bf[j][0] = f2tf(Bs[cur][ks + q][n]);
                bf[j][1] = f2tf(Bs[cur][ks + 4 + q][n]);
            }
#pragma unroll
            for (int i = 0; i < MT; ++i)
#pragma unroll
                for (int j = 0; j < NT; ++j)
                    mma8(acc[i][j], af[i], bf[j]);
        }
        if (more) {
            const int nxt = cur ^ 1;
            As[nxt][lk + 0][lr] = a0.x; As[nxt][lk + 1][lr] = a0.y;
            As[nxt][lk + 2][lr] = a0.z; As[nxt][lk + 3][lr] = a0.w;
            As[nxt][lk + 4][lr] = a1.x; As[nxt][lk + 5][lr] = a1.y;
            As[nxt][lk + 6][lr] = a1.z; As[nxt][lk + 7][lr] = a1.w;
            Bs[nxt][lk + 0][lr] = w0.x; Bs[nxt][lk + 1][lr] = w0.y;
            Bs[nxt][lk + 2][lr] = w0.z; Bs[nxt][lk + 3][lr] = w0.w;
            Bs[nxt][lk + 4][lr] = w1.x; Bs[nxt][lk + 5][lr] = w1.y;
            Bs[nxt][lk + 6][lr] = w1.z; Bs[nxt][lk + 7][lr] = w1.w;
        }
        __syncthreads();
    }

#pragma unroll
    for (int i = 0; i < MT; ++i) {
        int r0 = by * BM + mW + i * 16 + g;
#pragma unroll
        for (int j = 0; j < NT; ++j) {
            int c0 = bx * BN + nW + j * 8 + q * 2;
            float2 lo; lo.x = acc[i][j][0]; lo.y = acc[i][j][1];
            float2 hi; hi.x = acc[i][j][2]; hi.y = acc[i][j][3];
            if (HASBIAS) {
                float2 bv = *(const float2*)(bias + c0);
                lo.x += bv.x; lo.y += bv.y; hi.x += bv.x; hi.y += bv.y;
            }
            *(float2*)(C + (long)r0 * N + c0)       = lo;
            *(float2*)(C + (long)(r0 + 8) * N + c0) = hi;
        }
    }
}

// ---------------------------------------------------------------------------
// Attention core per (token, head)
// ---------------------------------------------------------------------------
__global__ __launch_bounds__(128)
void attn_core_k(const float* __restrict__ q, const float* __restrict__ k,
                 const float* __restrict__ v, float* __restrict__ av)
{
    __shared__ float qs[16][128], ks[16][128], vsm[16][128];
    __shared__ float sc[16][17];
    const int tid = threadIdx.x;
    const long token = blockIdx.x >> 2;
    const int h = blockIdx.x & 3;
    const long base = token * 16 * 512 + h * 128;

#pragma unroll
    for (int t = 0; t < 16; ++t) {
        qs[t][tid]  = q[base + (long)t * 512 + tid];
        ks[t][tid]  = k[base + (long)t * 512 + tid];
        vsm[t][tid] = v[base + (long)t * 512 + tid];
    }
    __syncthreads();

    for (int p = tid; p < 256; p += 128) {
        int t = p >> 4, u = p & 15;
        float acc = 0.0f;
#pragma unroll
        for (int d = 0; d < 128; ++d) acc += qs[t][d] * ks[u][d];
        sc[t][u] = acc / 11.3137084989847612f;   // / sqrt(128)
    }
    __syncthreads();

    if (tid < 16) {
        int t = tid;
        float mx = sc[t][0];
#pragma unroll
        for (int u = 1; u < 16; ++u) mx = fmaxf(mx, sc[t][u]);
        float e[16], sum = 0.0f;
#pragma unroll
        for (int u = 0; u < 16; ++u) { e[u] = expf(sc[t][u] - mx); sum += e[u]; }
#pragma unroll
        for (int u = 0; u < 16; ++u) sc[t][u] = e[u] / sum;
    }
    __syncthreads();

#pragma unroll
    for (int t = 0; t < 16; ++t) {
        float acc = 0.0f;
#pragma unroll
        for (int u = 0; u < 16; ++u) acc += sc[t][u] * vsm[u][tid];
        av[base + (long)t * 512 + tid] = acc;
    }
}

// ---------------------------------------------------------------------------
// h = x + permute(out_attn); hmean = mean_t(h)
// ---------------------------------------------------------------------------
__global__ void finalize_k(const float* __restrict__ xspk, const float* __restrict__ oat,
                           float* __restrict__ hout, float* __restrict__ hmean)
{
    int idx = blockIdx.x * blockDim.x + threadIdx.x;  // over NTOK*D_
    int d   = idx & (D_ - 1);
    int tok = idx >> 9;
    int b   = tok >> 9;
    int s   = tok & (S_ - 1);
    float sum = 0.0f;
#pragma unroll
    for (int t = 0; t < 16; ++t) {
        long hidx = (((long)(b * T_ + t)) * S_ + s) * D_ + d;
        float val = xspk[hidx] + oat[(((long)tok) * T_ + t) * D_ + d];
        hout[hidx] = val;
        sum += val;
    }
    hmean[(long)tok * D_ + d] = sum * (1.0f / 16.0f);
}

// ---------------------------------------------------------------------------
// host
// ---------------------------------------------------------------------------
extern "C" void kernel_launch(void* const* d_in, const int* in_sizes, int n_in,
                              void* d_out, int out_size)
{
    const int*   ids  = (const int*)d_in[0];
    const float* emb  = (const float*)d_in[1];
    const float* scal = (const float*)d_in[2];
    const float* Aall = (const float*)d_in[3];
    const float* Ball = (const float*)d_in[4];
    const float* Call = (const float*)d_in[5];
    const float* Dall = (const float*)d_in[6];
    const float* wq = (const float*)d_in[7];   const float* bq = (const float*)d_in[8];
    const float* wk = (const float*)d_in[9];   const float* bk = (const float*)d_in[10];
    const float* wv = (const float*)d_in[11];  const float* bv = (const float*)d_in[12];
    const float* wo = (const float*)d_in[13];  const float* bo = (const float*)d_in[14];
    const float* wout = (const float*)d_in[15];const float* bout = (const float*)d_in[16];
    float* out = (float*)d_out;

    float* arena = nullptr;
    cudaGetSymbolAddress((void**)&arena, g_arena);

    float* Hall   = arena + OFF_HALL;
    float* spk0   = arena + OFF_SPK0;
    float* spk1   = arena + OFF_SPK1;
    float* xp     = arena + OFF_XP;
    float* qb     = arena + OFF_Q;     // OU during SSM phase
    float* kb     = arena + OFF_K;
    float* vb     = arena + OFF_V;
    float* hmean  = arena + OFF_HM;
    int*   cnt    = (int*)(arena + OFF_CNT);   // 16*64 state counts
    int*   bar    = (int*)(arena + OFF_BAR);
    int*   flags  = (int*)(arena + OFF_FLG);
    float* OU     = qb;

    cudaFuncSetAttribute(state_layer_k,
                         cudaFuncAttributeMaxDynamicSharedMemorySize,
                         SMEM_STATE_BYTES);

    // -------- encode --------
    cudaMemsetAsync(spk0, 0, SPK * sizeof(float));
    cudaMemsetAsync(flags, 0, 48 * sizeof(int));
    encode_k<<<(NTOK * D_) / 256, 256>>>(ids, emb, scal, spk0, flags);

    // -------- SSM layers --------
    for (int l = 0; l < 2; ++l) {
        const float* Al = Aall + (long)l * DS_ * DS_;
        const float* Bl = Ball + (long)l * DS_ * D_;
        const float* Cl = Call + (long)l * D_ * DS_;
        const float* Dl = Dall + (long)l * D_ * D_;
        float* xin  = l ? spk1 : spk0;
        float* xout = l ? spk0 : spk1;
        int* fin  = flags + (l ? 16 : 0);
        int* fout = flags + (l ? 32 : 16);

        cudaMemsetAsync(cnt, 0, (CNT_INTS + 16) * sizeof(int));

        // persistent state recurrence: all 16 steps in one launch
        state_layer_k<<<NBLK, 256, SMEM_STATE_BYTES>>>(
            xin, Al, Bl, cnt, fin, Hall, bar);

        // hoisted output-path GEMMs (chains bitwise == R13); inactive-t rows skipped
        sgemm_k<false, false><<<dim3(4, NROWS / 128), 256>>>(
            Hall, Cl, nullptr, OU, NROWS, D_, DS_,
            (long)NROWS * DS_, (long)DS_, 0L, NROWS, fin);
        sgemm_k<true, false><<<dim3(4, NROWS / 128), 256>>>(
            xin, Dl, nullptr, OU, NROWS, D_, D_,
            (long)NROWS * D_, (long)D_, 0L, NROWS, fin);

        // fused output LIF over all 16 steps (writes zeros on inactive steps)
        out_fused_k<<<D_ / 4, 256>>>(OU, fin, xout, fout);
    }
    // after 2 layers: attention input = spk0 (B,T,S,D)

    // -------- attention (single-pass tf32; A read directly via PERM) --------
    const int MA = NROWS;  // 32768
    gemm_tf32_k<true, true><<<dim3(D_ / 128, MA / 128), 256>>>(spk0, wq, bq, qb, MA, D_, D_);
    gemm_tf32_k<true, true><<<dim3(D_ / 128, MA / 128), 256>>>(spk0, wk, bk, kb, MA, D_, D_);
    gemm_tf32_k<true, true><<<dim3(D_ / 128, MA / 128), 256>>>(spk0, wv, bv, vb, MA, D_, D_);
    attn_core_k<<<NTOK * 4, 128>>>(qb, kb, vb, spk1);           // av -> spk1
    gemm_tf32_k<true, false><<<dim3(D_ / 128, MA / 128), 256>>>(spk1, wo, bo, kb, MA, D_, D_);

    // -------- residual + mean + outputs --------
    float* hout = ((long)out_size >= LOGITS_SZ + H_SZ) ? (out + LOGITS_SZ) : xp;
    finalize_k<<<(NTOK * D_) / 256, 256>>>(spk0, kb, hout, hmean);

    // logits (single-pass tf32)
    gemm_tf32_k<true, false><<<dim3(V_ / 128, NTOK / 128), 256>>>(
        hmean, wout, bout, out, NTOK, V_, D_);
}